// round 14
// baseline (speedup 1.0000x reference)
#include <cuda_runtime.h>
#include <cstdint>
#include <cstddef>

#define IMH 224
#define IMW 224
#define NB  32
#define NO  64
#define PLANE (IMH * IMW)
#define TPI   196                 // tiles per image: 28 row-tiles x 7 col-tiles
#define NTILES (NB * TPI)         // 6272 tiles of 8 rows x 32 cols
#define GRIDSZ (148 * 5)
#define PADT  44                  // raw-tile row pitch (44 % 32 = 12 -> conflict-free)
#define TELEM (12 * 36)           // halo tile elements

__device__ __forceinline__ float fsqrt_approx(float x) {
    float r; asm("sqrt.approx.f32 %0, %1;" : "=f"(r) : "f"(x)); return r;
}
__device__ __forceinline__ float f2tf32f(float v) {
    float u; asm("cvt.rna.tf32.f32 %0, %1;" : "=f"(u) : "f"(v)); return u;
}
__device__ __forceinline__ void mma_tf32(float& c0, float& c1, float& c2, float& c3,
                                         uint32_t a0, uint32_t a1, uint32_t a2, uint32_t a3,
                                         float b0f, float b1f) {
    asm volatile(
        "mma.sync.aligned.m16n8k8.row.col.f32.tf32.tf32.f32 "
        "{%0,%1,%2,%3}, {%4,%5,%6,%7}, {%8,%9}, {%0,%1,%2,%3};"
        : "+f"(c0), "+f"(c1), "+f"(c2), "+f"(c3)
        : "r"(a0), "r"(a1), "r"(a2), "r"(a3),
          "r"(__float_as_uint(b0f)), "r"(__float_as_uint(b1f)));
}

// ---------------------------------------------------------------------------
// Persistent tf32 mma.sync kernel; hybrid A-fragment residency; 5 CTAs/SM.
// A fragments hold tf32(-2*w): m=0,1 cached in 32 registers for the whole
// kernel; m=2,3 read from SMEM per quarter-pass (L1 has headroom).
// Accumulators init to x2+w2 so c = x2 + w2 - 2 x.w; epilogue sqrt(|c|)+STG.
// CTA = 128 threads = 4 warps; tile = 8 pixel rows x 32 cols; warp w owns
// pixel rows {hh+w, hh+w+4}; 4 quarter-passes (one n8 tile each) keep B
// fragments at 16 regs.
// ---------------------------------------------------------------------------
__global__ __launch_bounds__(128, 5)
void conv_dist_mma(const float* __restrict__ x,
                   const float* __restrict__ wgt,
                   float* __restrict__ out) {
    __shared__ float sT[2][12 * PADT];                     // raw halo tiles
    __shared__ __align__(16) uint32_t sWf[16 * 32 * 4];    // [m][ks][lane][slot], -2w
    __shared__ __align__(8) float sX2[4][2][32];           // [warp][rt][pixel col]
    __shared__ float sW2[NO];

    const int tid  = threadIdx.x;
    const int wid  = tid >> 5;
    const int lane = tid & 31;
    const int g    = lane >> 2;
    const int tig  = lane & 3;

    // ---- one-time init: weight fragments (scaled by -2) + w2 ----
    for (int idx = tid; idx < 2048; idx += 128) {
        const int slot = idx & 3;
        const int ln   = (idx >> 2) & 31;
        const int ks   = (idx >> 7) & 3;
        const int m    = idx >> 9;
        const int row  = m * 16 + (ln >> 2) + ((slot & 1) ? 8 : 0);
        const int col  = ks * 8 + (ln & 3) + ((slot & 2) ? 4 : 0);
        const float v  = (col < 25) ? -2.f * wgt[row * 25 + col] : 0.f;
        sWf[idx] = __float_as_uint(f2tf32f(v));
    }
    if (tid < NO) {
        const float* wr = wgt + tid * 25;
        float s = 0.f;
#pragma unroll
        for (int t = 0; t < 25; t++) s = fmaf(wr[t], wr[t], s);
        sW2[tid] = s;
    }

    // per-thread tap offsets within raw tile: q=0..6, k=4q+tig (clamped to 24)
    uint32_t off[7];
#pragma unroll
    for (int q = 0; q < 7; q++) {
        int k = 4 * q + tig; if (k > 24) k = 24;
        off[q] = (uint32_t)((k / 5) * PADT + (k % 5));
    }
    // SMEM store offsets for halo tile load (idx fixed per thread)
    uint32_t soff[4];
#pragma unroll
    for (int r = 0; r < 4; r++) {
        const int idx = tid + 128 * r;
        soff[r] = (idx < TELEM) ? (uint32_t)((idx / 36) * PADT + (idx % 36)) : 0u;
    }
    __syncthreads();

    // ---- cache A fragments for m=0,1 + all w2 in registers ----
    uint4 afl[2][4];           // [m][ks] : 32 regs
#pragma unroll
    for (int m = 0; m < 2; m++)
#pragma unroll
        for (int ks = 0; ks < 4; ks++)
            afl[m][ks] = *(const uint4*)&sWf[((m * 4 + ks) * 32 + lane) * 4];
    float w2c[4][2];           // 8 regs
#pragma unroll
    for (int m = 0; m < 4; m++) {
        w2c[m][0] = sW2[m * 16 + g];
        w2c[m][1] = sW2[m * 16 + g + 8];
    }

    // ---- prologue: prefetch first halo tile into regs ----
    int tI = blockIdx.x;
    float pv[4];
    {
        const int b = tI / TPI, r2 = tI % TPI;
        const int hh = (r2 / 7) * 8, ww = (r2 % 7) * 32;
        const float* xb = x + (size_t)b * PLANE;
#pragma unroll
        for (int r = 0; r < 4; r++) {
            const int idx = tid + 128 * r;
            float v = 0.f;
            if (idx < TELEM) {
                const int trow = idx / 36, tcol = idx % 36;
                const int h = hh - 2 + trow, w = ww - 2 + tcol;
                if ((unsigned)h < IMH && (unsigned)w < IMW)
                    v = __ldg(xb + h * IMW + w);
            }
            pv[r] = v;
        }
    }

    int buf = 0;
    for (; tI < NTILES; tI += gridDim.x, buf ^= 1) {
        const int b = tI / TPI, r2 = tI % TPI;
        const int hh = (r2 / 7) * 8, ww = (r2 % 7) * 32;

        // ---- store prefetched tile ----
#pragma unroll
        for (int r = 0; r < 4; r++)
            if (tid + 128 * r < TELEM) sT[buf][soff[r]] = pv[r];
        __syncthreads();

        // ---- prefetch NEXT tile (hidden behind GEMM) ----
        const int nI = tI + gridDim.x;
        if (nI < NTILES) {
            const int nb = nI / TPI, nr2 = nI % TPI;
            const int nhh = (nr2 / 7) * 8, nww = (nr2 % 7) * 32;
            const float* xb = x + (size_t)nb * PLANE;
#pragma unroll
            for (int r = 0; r < 4; r++) {
                const int idx = tid + 128 * r;
                float v = 0.f;
                if (idx < TELEM) {
                    const int trow = idx / 36, tcol = idx % 36;
                    const int h = nhh - 2 + trow, w = nww - 2 + tcol;
                    if ((unsigned)h < IMH && (unsigned)w < IMW)
                        v = __ldg(xb + h * IMW + w);
                }
                pv[r] = v;
            }
        }

        const size_t obase = (size_t)b * NO * PLANE + (size_t)(hh + wid) * IMW + ww;
        const float* tb0 = &sT[buf][(wid) * PADT + g];
        const float* tb1 = &sT[buf][(wid + 4) * PADT + g];

        // ---- 4 quarter-passes: one n8 pixel tile each ----
#pragma unroll
        for (int nt = 0; nt < 4; nt++) {
            // B fragments for this quarter (raw fp32; HMMA truncates to tf32)
            float bfv[4][2][2];   // [ks][rt][b] : 16 regs
#pragma unroll
            for (int ks = 0; ks < 4; ks++) {
#pragma unroll
                for (int rt = 0; rt < 2; rt++) {
                    const float* tb = rt ? tb1 : tb0;
                    float b0, b1;
                    if (ks < 3) {
                        b0 = tb[off[2 * ks] + nt * 8];
                        b1 = tb[off[2 * ks + 1] + nt * 8];
                    } else {
                        b0 = (tig == 0) ? tb[off[6] + nt * 8] : 0.f;
                        b1 = 0.f;
                    }
                    bfv[ks][rt][0] = b0;
                    bfv[ks][rt][1] = b1;
                }
            }

            // x2 via quad-reduce + SMEM redistribution (per quarter)
#pragma unroll
            for (int rt = 0; rt < 2; rt++) {
                float s = 0.f;
#pragma unroll
                for (int ks = 0; ks < 4; ks++) {
                    s = fmaf(bfv[ks][rt][0], bfv[ks][rt][0], s);
                    s = fmaf(bfv[ks][rt][1], bfv[ks][rt][1], s);
                }
                s += __shfl_xor_sync(0xffffffffu, s, 1);
                s += __shfl_xor_sync(0xffffffffu, s, 2);
                if (tig == 0) sX2[wid][rt][nt * 8 + g] = s;
            }
            __syncwarp();
            float2 xp[2];
#pragma unroll
            for (int rt = 0; rt < 2; rt++)
                xp[rt] = *(const float2*)&sX2[wid][rt][nt * 8 + 2 * tig];

            // ---- 4 m-passes over channels ----
#pragma unroll
            for (int m = 0; m < 4; m++) {
                float c[2][4];
#pragma unroll
                for (int rt = 0; rt < 2; rt++) {
                    c[rt][0] = xp[rt].x + w2c[m][0];
                    c[rt][1] = xp[rt].y + w2c[m][0];
                    c[rt][2] = xp[rt].x + w2c[m][1];
                    c[rt][3] = xp[rt].y + w2c[m][1];
                }

#pragma unroll
                for (int ks = 0; ks < 4; ks++) {
                    uint4 a;
                    if (m < 2) a = afl[m][ks];
                    else       a = *(const uint4*)&sWf[((m * 4 + ks) * 32 + lane) * 4];
#pragma unroll
                    for (int rt = 0; rt < 2; rt++)
                        mma_tf32(c[rt][0], c[rt][1], c[rt][2], c[rt][3],
                                 a.x, a.y, a.z, a.w,
                                 bfv[ks][rt][0], bfv[ks][rt][1]);
                }

                const int ch0 = m * 16 + g;
                float* o0 = out + obase + (size_t)ch0 * PLANE;
                float* o1 = o0 + (size_t)8 * PLANE;

#pragma unroll
                for (int rt = 0; rt < 2; rt++) {
                    const int pc = nt * 8 + 2 * tig + rt * 4 * IMW;
                    float2 r0v, r1v;
                    r0v.x = fsqrt_approx(fabsf(c[rt][0]));
                    r0v.y = fsqrt_approx(fabsf(c[rt][1]));
                    r1v.x = fsqrt_approx(fabsf(c[rt][2]));
                    r1v.y = fsqrt_approx(fabsf(c[rt][3]));
                    *(float2*)(o0 + pc) = r0v;
                    *(float2*)(o1 + pc) = r1v;
                }
            }
        }
    }
}

extern "C" void kernel_launch(void* const* d_in, const int* in_sizes, int n_in,
                              void* d_out, int out_size) {
    (void)in_sizes; (void)n_in; (void)out_size;
    const float* x = (const float*)d_in[0];
    const float* w = (const float*)d_in[1];
    float* out = (float*)d_out;
    conv_dist_mma<<<GRIDSZ, 128>>>(x, w, out);
}

// round 15
// speedup vs baseline: 1.1012x; 1.1012x over previous
#include <cuda_runtime.h>
#include <cstdint>
#include <cstddef>

#define IMH 224
#define IMW 224
#define NB  32
#define NO  64
#define PLANE (IMH * IMW)
#define TPI   196                 // tiles per image: 28 row-tiles x 7 col-tiles
#define NTILES (NB * TPI)         // 6272 tiles of 8 rows x 32 cols
#define GRIDSZ (148 * 5)
#define PADT  44                  // raw-tile row pitch (44 % 32 = 12 -> conflict-free)
#define TELEM (12 * 36)           // halo tile elements

__device__ __forceinline__ float fsqrt_approx(float x) {
    float r; asm("sqrt.approx.f32 %0, %1;" : "=f"(r) : "f"(x)); return r;
}
// pack two f32 into bf16x2: lo = a, hi = b
__device__ __forceinline__ uint32_t pack_bf16(float a, float b) {
    uint32_t d;
    asm("cvt.rn.bf16x2.f32 %0, %1, %2;" : "=r"(d) : "f"(b), "f"(a));
    return d;
}
__device__ __forceinline__ void mma_bf16(float& c0, float& c1, float& c2, float& c3,
                                         uint32_t a0, uint32_t a1, uint32_t a2, uint32_t a3,
                                         uint32_t b0, uint32_t b1) {
    asm volatile(
        "mma.sync.aligned.m16n8k16.row.col.f32.bf16.bf16.f32 "
        "{%0,%1,%2,%3}, {%4,%5,%6,%7}, {%8,%9}, {%0,%1,%2,%3};"
        : "+f"(c0), "+f"(c1), "+f"(c2), "+f"(c3)
        : "r"(a0), "r"(a1), "r"(a2), "r"(a3), "r"(b0), "r"(b1));
}

// ---------------------------------------------------------------------------
// Persistent bf16 m16n8k16 mma.sync kernel; full register-resident A; 5 CTA/SM.
// A fragments hold bf16(-2*w) packed as bf16x2 (32 regs, constant across
// tiles). Accumulators init to x2+w2 (fp32), so c = x2 + w2 - 2 x.w after
// the K loop; epilogue = sqrt(|c|) + STG.64. x2/w2 computed in full fp32
// from the raw tile; only the cross term is bf16.
// CTA = 128 threads = 4 warps; tile = 8 pixel rows x 32 cols; warp w owns
// pixel rows {hh+w, hh+w+4} (rt=0,1); nh (pixel-column half) outer so only
// half the B fragments (16 regs) are live.
//
// m16n8k16 fragment mapping used (lane = 4g+tig):
//   A reg r: row = g + 8*(r&1), k-cols = 2tig + 8*(r>>1) + {0,1} (+16*kstep)
//   B reg 0: k-rows 2tig,2tig+1, col g ; B reg 1: k-rows 2tig+8,2tig+9
//   C: c0=(g,2tig) c1=(g,2tig+1) c2=(g+8,2tig) c3=(g+8,2tig+1)
// ---------------------------------------------------------------------------
__global__ __launch_bounds__(128, 5)
void conv_dist_mma(const float* __restrict__ x,
                   const float* __restrict__ wgt,
                   float* __restrict__ out) {
    __shared__ float sT[2][12 * PADT];                     // raw halo tiles
    __shared__ uint32_t sWf[4 * 2 * 32 * 4];               // [m][ks][lane][r] bf16x2(-2w)
    __shared__ __align__(8) float sX2[4][2][32];           // [warp][rt][pixel col]
    __shared__ float sW2[NO];

    const int tid  = threadIdx.x;
    const int wid  = tid >> 5;
    const int lane = tid & 31;
    const int g    = lane >> 2;
    const int tig  = lane & 3;

    // ---- one-time init: packed bf16 A-fragment table (-2w) + fp32 w2 ----
    for (int idx = tid; idx < 1024; idx += 128) {
        const int r  = idx & 3;
        const int ln = (idx >> 2) & 31;
        const int ks = (idx >> 7) & 1;
        const int m  = idx >> 8;
        const int row = m * 16 + (ln >> 2) + ((r & 1) ? 8 : 0);
        const int c0  = ks * 16 + 2 * (ln & 3) + ((r & 2) ? 8 : 0);
        const float v0 = (c0 < 25)     ? -2.f * wgt[row * 25 + c0]     : 0.f;
        const float v1 = (c0 + 1 < 25) ? -2.f * wgt[row * 25 + c0 + 1] : 0.f;
        sWf[idx] = pack_bf16(v0, v1);
    }
    if (tid < NO) {
        const float* wr = wgt + tid * 25;
        float s = 0.f;
#pragma unroll
        for (int t = 0; t < 25; t++) s = fmaf(wr[t], wr[t], s);
        sW2[tid] = s;
    }

    // per-thread tap offsets: k-list {2t,2t+1,2t+8,2t+9,16+2t,17+2t,24}
    uint32_t off[7];
    {
        const int kl[7] = { 2 * tig, 2 * tig + 1, 2 * tig + 8, 2 * tig + 9,
                            16 + 2 * tig, 17 + 2 * tig, 24 };
#pragma unroll
        for (int i = 0; i < 7; i++)
            off[i] = (uint32_t)((kl[i] / 5) * PADT + (kl[i] % 5));
    }
    // SMEM store offsets for halo tile load
    uint32_t soff[4];
#pragma unroll
    for (int r = 0; r < 4; r++) {
        const int idx = tid + 128 * r;
        soff[r] = (idx < TELEM) ? (uint32_t)((idx / 36) * PADT + (idx % 36)) : 0u;
    }
    __syncthreads();

    // ---- cache ALL A fragments in registers (32 regs, constant) ----
    uint4 af[4][2];            // [m][ks]
#pragma unroll
    for (int m = 0; m < 4; m++)
#pragma unroll
        for (int ks = 0; ks < 2; ks++)
            af[m][ks] = *(const uint4*)&sWf[((m * 2 + ks) * 32 + lane) * 4];

    // ---- prologue: prefetch first halo tile into regs ----
    int tI = blockIdx.x;
    float pv[4];
    {
        const int b = tI / TPI, r2 = tI % TPI;
        const int hh = (r2 / 7) * 8, ww = (r2 % 7) * 32;
        const float* xb = x + (size_t)b * PLANE;
#pragma unroll
        for (int r = 0; r < 4; r++) {
            const int idx = tid + 128 * r;
            float v = 0.f;
            if (idx < TELEM) {
                const int trow = idx / 36, tcol = idx % 36;
                const int h = hh - 2 + trow, w = ww - 2 + tcol;
                if ((unsigned)h < IMH && (unsigned)w < IMW)
                    v = __ldg(xb + h * IMW + w);
            }
            pv[r] = v;
        }
    }

    int buf = 0;
    for (; tI < NTILES; tI += gridDim.x, buf ^= 1) {
        const int b = tI / TPI, r2 = tI % TPI;
        const int hh = (r2 / 7) * 8, ww = (r2 % 7) * 32;

        // ---- store prefetched tile ----
#pragma unroll
        for (int r = 0; r < 4; r++)
            if (tid + 128 * r < TELEM) sT[buf][soff[r]] = pv[r];
        __syncthreads();

        // ---- prefetch NEXT tile (hidden behind GEMM) ----
        const int nI = tI + gridDim.x;
        if (nI < NTILES) {
            const int nb = nI / TPI, nr2 = nI % TPI;
            const int nhh = (nr2 / 7) * 8, nww = (nr2 % 7) * 32;
            const float* xb = x + (size_t)nb * PLANE;
#pragma unroll
            for (int r = 0; r < 4; r++) {
                const int idx = tid + 128 * r;
                float v = 0.f;
                if (idx < TELEM) {
                    const int trow = idx / 36, tcol = idx % 36;
                    const int h = nhh - 2 + trow, w = nww - 2 + tcol;
                    if ((unsigned)h < IMH && (unsigned)w < IMW)
                        v = __ldg(xb + h * IMW + w);
                }
                pv[r] = v;
            }
        }

        const size_t obase = (size_t)b * NO * PLANE + (size_t)(hh + wid) * IMW + ww;
        const float* tb0 = &sT[buf][(wid) * PADT + g];
        const float* tb1 = &sT[buf][(wid + 4) * PADT + g];

        // ---- process pixel-column halves: nt = 2*nh + nt2 ----
#pragma unroll
        for (int nh = 0; nh < 2; nh++) {
            // B fragments (bf16x2 packed) + fp32 x2 partials
            uint32_t bfv[2][2][2][2];   // [ks][rt][nt2][reg]
#pragma unroll
            for (int rt = 0; rt < 2; rt++) {
                const float* tb = rt ? tb1 : tb0;
#pragma unroll
                for (int nt2 = 0; nt2 < 2; nt2++) {
                    const int nc = (2 * nh + nt2) * 8;
                    const float v0 = tb[off[0] + nc];
                    const float v1 = tb[off[1] + nc];
                    const float v2 = tb[off[2] + nc];
                    const float v3 = tb[off[3] + nc];
                    const float v4 = tb[off[4] + nc];
                    const float v5 = tb[off[5] + nc];
                    const float v6 = (tig == 0) ? tb[off[6] + nc] : 0.f;
                    bfv[0][rt][nt2][0] = pack_bf16(v0, v1);
                    bfv[0][rt][nt2][1] = pack_bf16(v2, v3);
                    bfv[1][rt][nt2][0] = pack_bf16(v4, v5);
                    bfv[1][rt][nt2][1] = pack_bf16(v6, 0.f);

                    // fp32 x2 partial (taps of this thread; quad covers 0..24)
                    float s = v0 * v0;
                    s = fmaf(v1, v1, s); s = fmaf(v2, v2, s);
                    s = fmaf(v3, v3, s); s = fmaf(v4, v4, s);
                    s = fmaf(v5, v5, s); s = fmaf(v6, v6, s);
                    s += __shfl_xor_sync(0xffffffffu, s, 1);
                    s += __shfl_xor_sync(0xffffffffu, s, 2);
                    if (tig == 0) sX2[wid][rt][(2 * nh + nt2) * 8 + g] = s;
                }
            }
            __syncwarp();

            float2 xp[2][2];
#pragma unroll
            for (int rt = 0; rt < 2; rt++)
#pragma unroll
                for (int nt2 = 0; nt2 < 2; nt2++)
                    xp[rt][nt2] = *(const float2*)
                        &sX2[wid][rt][(2 * nh + nt2) * 8 + 2 * tig];

            // ---- 4 m-passes over channels (A from registers) ----
#pragma unroll
            for (int m = 0; m < 4; m++) {
                const int ch0 = m * 16 + g;
                const float w20 = sW2[ch0];
                const float w21 = sW2[ch0 + 8];

                float c[2][2][4];
#pragma unroll
                for (int rt = 0; rt < 2; rt++)
#pragma unroll
                    for (int nt2 = 0; nt2 < 2; nt2++) {
                        c[rt][nt2][0] = xp[rt][nt2].x + w20;
                        c[rt][nt2][1] = xp[rt][nt2].y + w20;
                        c[rt][nt2][2] = xp[rt][nt2].x + w21;
                        c[rt][nt2][3] = xp[rt][nt2].y + w21;
                    }

#pragma unroll
                for (int ks = 0; ks < 2; ks++)
#pragma unroll
                    for (int rt = 0; rt < 2; rt++)
#pragma unroll
                        for (int nt2 = 0; nt2 < 2; nt2++)
                            mma_bf16(c[rt][nt2][0], c[rt][nt2][1],
                                     c[rt][nt2][2], c[rt][nt2][3],
                                     af[m][ks].x, af[m][ks].y,
                                     af[m][ks].z, af[m][ks].w,
                                     bfv[ks][rt][nt2][0], bfv[ks][rt][nt2][1]);

                float* o0 = out + obase + (size_t)ch0 * PLANE;
                float* o1 = o0 + (size_t)8 * PLANE;

#pragma unroll
                for (int rt = 0; rt < 2; rt++) {
#pragma unroll
                    for (int nt2 = 0; nt2 < 2; nt2++) {
                        const int nt = 2 * nh + nt2;
                        const int pc = nt * 8 + 2 * tig + rt * 4 * IMW;
                        float2 r0v, r1v;
                        r0v.x = fsqrt_approx(fabsf(c[rt][nt2][0]));
                        r0v.y = fsqrt_approx(fabsf(c[rt][nt2][1]));
                        r1v.x = fsqrt_approx(fabsf(c[rt][nt2][2]));
                        r1v.y = fsqrt_approx(fabsf(c[rt][nt2][3]));
                        *(float2*)(o0 + pc) = r0v;
                        *(float2*)(o1 + pc) = r1v;
                    }
                }
            }
        }
    }
}

extern "C" void kernel_launch(void* const* d_in, const int* in_sizes, int n_in,
                              void* d_out, int out_size) {
    (void)in_sizes; (void)n_in; (void)out_size;
    const float* x = (const float*)d_in[0];
    const float* w = (const float*)d_in[1];
    float* out = (float*)d_out;
    conv_dist_mma<<<GRIDSZ, 128>>>(x, w, out);
}